// round 5
// baseline (speedup 1.0000x reference)
#include <cuda_runtime.h>
#include <math.h>

// B=4096, N=16384, fp32. HBM-bound stencil:
//   x = nan_checker(output); g[i] = x[i]-x[(i-1)%N];
//   out = (g < mean-4*std || g > mean+4*std) ? 0 : x
//
// R5: column-stripe blocks with MODERATE row batching (8 rows/block,
// 4096 blocks) — bounds hoisted to registers (sqrt amortized 8x) while
// keeping enough blocks for wave-level load balancing. Default-cached
// x loads (lane0 prev re-reads stay L2-hit), streaming stores.

#define K_SIGMA 4.0f
#define VPT 2
#define TPB 256
#define ROWS_PER_BLOCK 8

__device__ __forceinline__ float sanitize(float v) {
    return isfinite(v) ? v : 0.0f;
}

__device__ __forceinline__ float4 sanitize4(float4 v) {
    v.x = sanitize(v.x); v.y = sanitize(v.y);
    v.z = sanitize(v.z); v.w = sanitize(v.w);
    return v;
}

__device__ __forceinline__ float4 apply4(float4 xv, float prev,
                                         float4 lo, float4 hi) {
    float4 o; float g;
    g = xv.x - prev;  o.x = (g < lo.x || g > hi.x) ? 0.0f : xv.x;
    g = xv.y - xv.x;  o.y = (g < lo.y || g > hi.y) ? 0.0f : xv.y;
    g = xv.z - xv.y;  o.z = (g < lo.z || g > hi.z) ? 0.0f : xv.z;
    g = xv.w - xv.z;  o.w = (g < lo.w || g > hi.w) ? 0.0f : xv.w;
    return o;
}

__global__ __launch_bounds__(TPB)
void correction_kernel(const float* __restrict__ x,
                       const float* __restrict__ mean_grad,
                       const float* __restrict__ var_grad,
                       float* __restrict__ out,
                       int N, int B)
{
    const unsigned lane = threadIdx.x & 31u;

    // Fixed column vectors for this thread (stable across rows).
    int cv[VPT];
    #pragma unroll
    for (int i = 0; i < VPT; i++)
        cv[i] = blockIdx.x * (TPB * VPT) + i * TPB + threadIdx.x;

    // Bounds -> registers, once per block (amortized over 8 rows).
    const float4* mg4 = reinterpret_cast<const float4*>(mean_grad);
    const float4* vg4 = reinterpret_cast<const float4*>(var_grad);
    float4 lo[VPT], hi[VPT];
    #pragma unroll
    for (int i = 0; i < VPT; i++) {
        float4 m = __ldg(&mg4[cv[i]]);
        float4 v = __ldg(&vg4[cv[i]]);
        float4 s;
        s.x = K_SIGMA * sqrtf(v.x);
        s.y = K_SIGMA * sqrtf(v.y);
        s.z = K_SIGMA * sqrtf(v.z);
        s.w = K_SIGMA * sqrtf(v.w);
        lo[i] = make_float4(m.x - s.x, m.y - s.y, m.z - s.z, m.w - s.w);
        hi[i] = make_float4(m.x + s.x, m.y + s.y, m.z + s.z, m.w + s.w);
    }

    int pc[VPT];
    #pragma unroll
    for (int i = 0; i < VPT; i++)
        pc[i] = (cv[i] == 0) ? (N - 1) : (cv[i] * 4 - 1);

    const int row0 = blockIdx.y * ROWS_PER_BLOCK;
    const int row1 = (row0 + ROWS_PER_BLOCK < B) ? row0 + ROWS_PER_BLOCK : B;

    for (int row = row0; row < row1; row++) {
        const long long rowOff = (long long)row * N;
        const float4* xr  = reinterpret_cast<const float4*>(x + rowOff);
        float4*       or4 = reinterpret_cast<float4*>(out + rowOff);

        float4 xv[VPT];
        #pragma unroll
        for (int i = 0; i < VPT; i++)
            xv[i] = sanitize4(xr[cv[i]]);

        #pragma unroll
        for (int i = 0; i < VPT; i++) {
            float prev = __shfl_up_sync(0xFFFFFFFFu, xv[i].w, 1);
            if (lane == 0)
                prev = sanitize(__ldg(&x[rowOff + pc[i]]));
            __stcs(&or4[cv[i]], apply4(xv[i], prev, lo[i], hi[i]));
        }
    }
}

extern "C" void kernel_launch(void* const* d_in, const int* in_sizes, int n_in,
                              void* d_out, int out_size) {
    const float* x         = (const float*)d_in[0];
    const float* mean_grad = (const float*)d_in[1];
    const float* var_grad  = (const float*)d_in[2];
    float* out             = (float*)d_out;

    int N = in_sizes[1];                       // 16384
    long long total = (long long)in_sizes[0];  // B*N
    int B = (int)(total / N);

    int nStripes = N / (TPB * VPT * 4);        // 8
    int rowBlocks = (B + ROWS_PER_BLOCK - 1) / ROWS_PER_BLOCK;  // 512
    dim3 grid(nStripes, rowBlocks);            // (8, 512) = 4096 blocks
    correction_kernel<<<grid, TPB>>>(x, mean_grad, var_grad, out, N, B);
}

// round 6
// speedup vs baseline: 1.0613x; 1.0613x over previous
#include <cuda_runtime.h>
#include <math.h>

// B=4096, N=16384, fp32. HBM-bound stencil:
//   x = nan_checker(output); g[i] = x[i]-x[(i-1)%N];
//   out = (g < mean-4*std || g > mean+4*std) ? 0 : x
//
// R6: R2's winning grid shape (32768 blocks, best load balance / 1us
// bench-ncu gap) + Blackwell 256-bit vector memory ops. One v8 (8 floats,
// 32B) per thread: 3 v8 loads + 1 v8 store instead of 10 x 128-bit ops.
// Left neighbor via warp shuffle of element 7; lane0 does one L2-hit
// scalar load.

#define K_SIGMA 4.0f
#define TPB 256

__device__ __forceinline__ float sanitize(float v) {
    return isfinite(v) ? v : 0.0f;
}

__device__ __forceinline__ void ldg_nc_v8(const float* p, float* r) {
    asm volatile(
        "ld.global.nc.v8.f32 {%0,%1,%2,%3,%4,%5,%6,%7}, [%8];"
        : "=f"(r[0]), "=f"(r[1]), "=f"(r[2]), "=f"(r[3]),
          "=f"(r[4]), "=f"(r[5]), "=f"(r[6]), "=f"(r[7])
        : "l"(p));
}

__device__ __forceinline__ void stg_cs_v8(float* p, const float* r) {
    asm volatile(
        "st.global.cs.v8.f32 [%0], {%1,%2,%3,%4,%5,%6,%7,%8};"
        :: "l"(p),
           "f"(r[0]), "f"(r[1]), "f"(r[2]), "f"(r[3]),
           "f"(r[4]), "f"(r[5]), "f"(r[6]), "f"(r[7])
        : "memory");
}

__global__ __launch_bounds__(TPB)
void correction_kernel(const float* __restrict__ x,
                       const float* __restrict__ mean_grad,
                       const float* __restrict__ var_grad,
                       float* __restrict__ out,
                       int N)
{
    const int row = blockIdx.y;
    const long long rowOff = (long long)row * N;
    const int cv = blockIdx.x * TPB + threadIdx.x;   // v8 index in row
    const long long col0 = (long long)cv * 8;
    const unsigned lane = threadIdx.x & 31u;

    // 256-bit loads: x, mean, var (stats are L2-resident, reused 4096x).
    float r[8], m[8], vv[8];
    ldg_nc_v8(x + rowOff + col0, r);
    ldg_nc_v8(mean_grad + col0, m);
    ldg_nc_v8(var_grad + col0, vv);

    #pragma unroll
    for (int j = 0; j < 8; j++) r[j] = sanitize(r[j]);

    // Left neighbor of element 0: previous lane's element 7.
    float prev = __shfl_up_sync(0xFFFFFFFFu, r[7], 1);
    if (lane == 0) {
        long long pc = (cv == 0) ? (N - 1) : (col0 - 1);
        prev = sanitize(__ldg(&x[rowOff + pc]));
    }

    float o[8];
    #pragma unroll
    for (int j = 0; j < 8; j++) {
        float p = (j == 0) ? prev : r[j - 1];
        float g = r[j] - p;
        float s = K_SIGMA * sqrtf(vv[j]);
        o[j] = (g < m[j] - s || g > m[j] + s) ? 0.0f : r[j];
    }

    stg_cs_v8(out + rowOff + col0, o);
}

extern "C" void kernel_launch(void* const* d_in, const int* in_sizes, int n_in,
                              void* d_out, int out_size) {
    const float* x         = (const float*)d_in[0];
    const float* mean_grad = (const float*)d_in[1];
    const float* var_grad  = (const float*)d_in[2];
    float* out             = (float*)d_out;

    int N = in_sizes[1];                       // 16384
    long long total = (long long)in_sizes[0];  // B*N
    int B = (int)(total / N);

    int vecsPerRow = N / 8;                    // 2048
    dim3 grid(vecsPerRow / TPB, B);            // (8, 4096) = 32768 blocks
    correction_kernel<<<grid, TPB>>>(x, mean_grad, var_grad, out, N);
}

// round 7
// speedup vs baseline: 1.0749x; 1.0129x over previous
#include <cuda_runtime.h>
#include <math.h>

// B=4096, N=16384, fp32. HBM-bound stencil:
//   x = nan_checker(output); g[i] = x[i]-x[(i-1)%N];
//   out = (|g - mean| > 4*sqrt(var)) ? 0 : x
//
// R7: R6 (v8 256-bit memory ops, 32768 blocks) + algebraic sqrt removal:
//   |g-m| > 4*sqrt(v)  <=>  (g-m)^2 > 16*v     (both sides >= 0)
// Per element: 2 subs, 1 mul, 1 fma-compare. No MUFU in the hot path.

#define K_SIGMA 4.0f
#define K2 (K_SIGMA * K_SIGMA)   // 16
#define TPB 256

__device__ __forceinline__ float sanitize(float v) {
    return isfinite(v) ? v : 0.0f;
}

__device__ __forceinline__ void ldg_nc_v8(const float* p, float* r) {
    asm volatile(
        "ld.global.nc.v8.f32 {%0,%1,%2,%3,%4,%5,%6,%7}, [%8];"
        : "=f"(r[0]), "=f"(r[1]), "=f"(r[2]), "=f"(r[3]),
          "=f"(r[4]), "=f"(r[5]), "=f"(r[6]), "=f"(r[7])
        : "l"(p));
}

__device__ __forceinline__ void stg_cs_v8(float* p, const float* r) {
    asm volatile(
        "st.global.cs.v8.f32 [%0], {%1,%2,%3,%4,%5,%6,%7,%8};"
        :: "l"(p),
           "f"(r[0]), "f"(r[1]), "f"(r[2]), "f"(r[3]),
           "f"(r[4]), "f"(r[5]), "f"(r[6]), "f"(r[7])
        : "memory");
}

__global__ __launch_bounds__(TPB)
void correction_kernel(const float* __restrict__ x,
                       const float* __restrict__ mean_grad,
                       const float* __restrict__ var_grad,
                       float* __restrict__ out,
                       int N)
{
    const int row = blockIdx.y;
    const long long rowOff = (long long)row * N;
    const int cv = blockIdx.x * TPB + threadIdx.x;   // v8 index in row
    const long long col0 = (long long)cv * 8;
    const unsigned lane = threadIdx.x & 31u;

    float r[8], m[8], vv[8];
    ldg_nc_v8(x + rowOff + col0, r);
    ldg_nc_v8(mean_grad + col0, m);
    ldg_nc_v8(var_grad + col0, vv);

    #pragma unroll
    for (int j = 0; j < 8; j++) r[j] = sanitize(r[j]);

    // Left neighbor of element 0: previous lane's element 7 (L2-hit scalar
    // load for lane 0).
    float prev = __shfl_up_sync(0xFFFFFFFFu, r[7], 1);
    if (lane == 0) {
        long long pc = (cv == 0) ? (N - 1) : (col0 - 1);
        prev = sanitize(__ldg(&x[rowOff + pc]));
    }

    float o[8];
    #pragma unroll
    for (int j = 0; j < 8; j++) {
        float p = (j == 0) ? prev : r[j - 1];
        float d = (r[j] - p) - m[j];
        // mask iff d*d > 16*var  (equiv. to |d| > 4*sqrt(var))
        o[j] = (d * d > K2 * vv[j]) ? 0.0f : r[j];
    }

    stg_cs_v8(out + rowOff + col0, o);
}

extern "C" void kernel_launch(void* const* d_in, const int* in_sizes, int n_in,
                              void* d_out, int out_size) {
    const float* x         = (const float*)d_in[0];
    const float* mean_grad = (const float*)d_in[1];
    const float* var_grad  = (const float*)d_in[2];
    float* out             = (float*)d_out;

    int N = in_sizes[1];                       // 16384
    long long total = (long long)in_sizes[0];  // B*N
    int B = (int)(total / N);

    int vecsPerRow = N / 8;                    // 2048
    dim3 grid(vecsPerRow / TPB, B);            // (8, 4096) = 32768 blocks
    correction_kernel<<<grid, TPB>>>(x, mean_grad, var_grad, out, N);
}

// round 8
// speedup vs baseline: 1.0779x; 1.0027x over previous
#include <cuda_runtime.h>
#include <math.h>

// B=4096, N=16384, fp32. HBM-bound stencil:
//   x = nan_checker(output); g[i] = x[i]-x[(i-1)%N];
//   out = (|g - mean| > 4*sqrt(var)) ? 0 : x    [via (g-m)^2 > 16*var]
//
// R8: R7 (v8 256-bit ops, squared compare, no MUFU) +
//   - 2 front-batched v8 per thread (bigger DRAM burst grain, half the blocks)
//   - default write-back stores (drop .cs: let L2 coalesce write bursts)

#define K_SIGMA 4.0f
#define K2 (K_SIGMA * K_SIGMA)   // 16
#define TPB 256
#define VPT 2                    // v8 vectors per thread

__device__ __forceinline__ float sanitize(float v) {
    return isfinite(v) ? v : 0.0f;
}

__device__ __forceinline__ void ldg_nc_v8(const float* p, float* r) {
    asm volatile(
        "ld.global.nc.v8.f32 {%0,%1,%2,%3,%4,%5,%6,%7}, [%8];"
        : "=f"(r[0]), "=f"(r[1]), "=f"(r[2]), "=f"(r[3]),
          "=f"(r[4]), "=f"(r[5]), "=f"(r[6]), "=f"(r[7])
        : "l"(p));
}

__device__ __forceinline__ void stg_v8(float* p, const float* r) {
    asm volatile(
        "st.global.v8.f32 [%0], {%1,%2,%3,%4,%5,%6,%7,%8};"
        :: "l"(p),
           "f"(r[0]), "f"(r[1]), "f"(r[2]), "f"(r[3]),
           "f"(r[4]), "f"(r[5]), "f"(r[6]), "f"(r[7])
        : "memory");
}

__global__ __launch_bounds__(TPB)
void correction_kernel(const float* __restrict__ x,
                       const float* __restrict__ mean_grad,
                       const float* __restrict__ var_grad,
                       float* __restrict__ out,
                       int N)
{
    const int row = blockIdx.y;
    const long long rowOff = (long long)row * N;
    const unsigned lane = threadIdx.x & 31u;
    const int baseVec = blockIdx.x * (TPB * VPT);

    // Front-batched: both x v8 loads in flight before anything else.
    int cv[VPT];
    float r[VPT][8];
    #pragma unroll
    for (int i = 0; i < VPT; i++) {
        cv[i] = baseVec + i * TPB + threadIdx.x;
        ldg_nc_v8(x + rowOff + (long long)cv[i] * 8, r[i]);
    }

    #pragma unroll
    for (int i = 0; i < VPT; i++) {
        float m[8], vv[8];
        ldg_nc_v8(mean_grad + (long long)cv[i] * 8, m);
        ldg_nc_v8(var_grad  + (long long)cv[i] * 8, vv);

        #pragma unroll
        for (int j = 0; j < 8; j++) r[i][j] = sanitize(r[i][j]);

        // Left neighbor of element 0: previous lane's element 7.
        float prev = __shfl_up_sync(0xFFFFFFFFu, r[i][7], 1);
        if (lane == 0) {
            long long pc = (cv[i] == 0) ? (N - 1) : ((long long)cv[i] * 8 - 1);
            prev = sanitize(__ldg(&x[rowOff + pc]));
        }

        float o[8];
        #pragma unroll
        for (int j = 0; j < 8; j++) {
            float p = (j == 0) ? prev : r[i][j - 1];
            float d = (r[i][j] - p) - m[j];
            o[j] = (d * d > K2 * vv[j]) ? 0.0f : r[i][j];
        }

        stg_v8(out + rowOff + (long long)cv[i] * 8, o);
    }
}

extern "C" void kernel_launch(void* const* d_in, const int* in_sizes, int n_in,
                              void* d_out, int out_size) {
    const float* x         = (const float*)d_in[0];
    const float* mean_grad = (const float*)d_in[1];
    const float* var_grad  = (const float*)d_in[2];
    float* out             = (float*)d_out;

    int N = in_sizes[1];                       // 16384
    long long total = (long long)in_sizes[0];  // B*N
    int B = (int)(total / N);

    int vecsPerRow = N / 8;                    // 2048
    dim3 grid(vecsPerRow / (TPB * VPT), B);    // (4, 4096) = 16384 blocks
    correction_kernel<<<grid, TPB>>>(x, mean_grad, var_grad, out, N);
}